// round 13
// baseline (speedup 1.0000x reference)
#include <cuda_runtime.h>
#include <math.h>

#define BN 1024
#define DN 128
#define HN 128
#define LN_EPS 1e-5f

__device__ float g_dmT[DN * BN];    // [d][i]
__device__ float g_xT[DN * BN];     // [d][i]
__device__ unsigned g_count = 0;
__device__ unsigned g_sense = 0;

typedef unsigned long long ull;
typedef unsigned int uint;

// ---------------------------------------------------------------------------
// smem layout (floats)
// ---------------------------------------------------------------------------
#define OFF_W    0                 /* 3 * 16384 = 49152 (Wd | Wa | Wr)      */
#define OFF_XS   49152             /* 1088                                   */
#define OFF_UN   50240             /* union: sv(1024u)+ps(1024) | ds+hs 2176 */
#define OFF_CB   52416             /* Wt bd ba br gamma beta : 6*128 = 768   */
#define OFF_RED  53184             /* redS 128 | redQ 128                    */
#define OFF_WSUM 53440             /* 16 */
#define OFF_RTAU 53456             /* 8  */
#define OFF_MS   53464             /* 16 */
#define SMEM_FLOATS 53484
#define SMEM_BYTES  (SMEM_FLOATS * 4)

#define CHW 68
#define IDX(k, r) ((((k) >> 3) * CHW) + (((k) & 7) << 3) + (r))

// ---------------------------------------------------------------------------
__device__ __forceinline__ uint encf(float f) {
    uint u = __float_as_uint(f);
    return u ^ ((u & 0x80000000u) ? 0xFFFFFFFFu : 0x80000000u);
}
__device__ __forceinline__ float decf(uint u) {
    u ^= (u & 0x80000000u) ? 0x80000000u : 0xFFFFFFFFu;
    return __uint_as_float(u);
}

__device__ __forceinline__ void g64(int t) {
    asm volatile("bar.sync %0, 64;"  :: "r"(1 + (t >> 6)) : "memory");
}
__device__ __forceinline__ void g128(int t) {
    asm volatile("bar.sync %0, 128;" :: "r"(9 + (t >> 7)) : "memory");
}
__device__ __forceinline__ void g256(int t) {
    asm volatile("bar.sync %0, 256;" :: "r"(13 + (t >> 8)) : "memory");
}

template<int K, int J>
__device__ __forceinline__ void sstage(uint* __restrict__ sv, int t) {
    int i = ((t & ~(J - 1)) << 1) | (t & (J - 1));
    int ixj = i | J;
    uint a = sv[i];
    uint b = sv[ixj];
    if ((a > b) == ((i & K) == 0)) { sv[i] = b; sv[ixj] = a; }
}

__device__ __forceinline__ void rtail(uint& r0, uint& r1, int p0, bool up) {
    uint lo = min(r0, r1), hi = max(r0, r1);
    r0 = up ? lo : hi;
    r1 = up ? hi : lo;
    #pragma unroll
    for (int j = 16; j > 0; j >>= 1) {
        bool km = (((p0 & j) == 0) == up);
        uint o0 = __shfl_xor_sync(0xffffffffu, r0, j);
        r0 = km ? min(r0, o0) : max(r0, o0);
        uint o1 = __shfl_xor_sync(0xffffffffu, r1, j);
        r1 = km ? min(r1, o1) : max(r1, o1);
    }
}

// ---------------------------------------------------------------------------
__device__ __forceinline__ ull fma2(ull a, ull b, ull c) {
    ull d;
    asm("fma.rn.f32x2 %0, %1, %2, %3;" : "=l"(d) : "l"(a), "l"(b), "l"(c));
    return d;
}
__device__ __forceinline__ ull add2(ull a, ull b) {
    ull d;
    asm("add.rn.f32x2 %0, %1, %2;" : "=l"(d) : "l"(a), "l"(b));
    return d;
}
__device__ __forceinline__ ull dup2(float w) {
    ull d;
    asm("mov.b64 %0, {%1, %1};" : "=l"(d) : "r"(__float_as_uint(w)));
    return d;
}

// weights from smem: thread t, half h: wv[c] = chunk (c*2+h)
__device__ __forceinline__ void lw4s(const float* __restrict__ wbase,
                                     int t, int half, float4 wv[4])
{
    #pragma unroll
    for (int c = 0; c < 4; c++)
        wv[c] = *(const float4*)(wbase + (((c * 2 + half) * 512 + t) << 2));
}

__device__ __forceinline__ void mv_acc4(const float* __restrict__ ip, int kb,
                                        const float4 wv[4], ull A[16])
{
    #pragma unroll
    for (int kl = 0; kl < 4; kl++) {
        ulonglong2 q0 = *(const ulonglong2*)(ip + (kb + kl) * 8);
        ulonglong2 q1 = *(const ulonglong2*)(ip + (kb + kl) * 8 + 4);
        #pragma unroll
        for (int c = 0; c < 4; c++) {
            ull w2 = dup2(((const float*)&wv[c])[kl]);
            A[c * 4 + 0] = fma2(q0.x, w2, A[c * 4 + 0]);
            A[c * 4 + 1] = fma2(q0.y, w2, A[c * 4 + 1]);
            A[c * 4 + 2] = fma2(q1.x, w2, A[c * 4 + 2]);
            A[c * 4 + 3] = fma2(q1.y, w2, A[c * 4 + 3]);
        }
    }
}

__device__ __forceinline__ void butterfly16x2(ull A[16], ull B[16], int m)
{
    #pragma unroll
    for (int j = 0; j < 8; j++) {
        ull sa = (m & 8) ? A[j] : A[j + 8];
        ull sb = (m & 8) ? B[j] : B[j + 8];
        ull ca = __shfl_xor_sync(0xffffffffu, sa, 8);
        ull cb = __shfl_xor_sync(0xffffffffu, sb, 8);
        A[j] = add2((m & 8) ? A[j + 8] : A[j], ca);
        B[j] = add2((m & 8) ? B[j + 8] : B[j], cb);
    }
    #pragma unroll
    for (int j = 0; j < 4; j++) {
        ull sa = (m & 4) ? A[j] : A[j + 4];
        ull sb = (m & 4) ? B[j] : B[j + 4];
        ull ca = __shfl_xor_sync(0xffffffffu, sa, 4);
        ull cb = __shfl_xor_sync(0xffffffffu, sb, 4);
        A[j] = add2((m & 4) ? A[j + 4] : A[j], ca);
        B[j] = add2((m & 4) ? B[j + 4] : B[j], cb);
    }
    #pragma unroll
    for (int j = 0; j < 2; j++) {
        ull sa = (m & 2) ? A[j] : A[j + 2];
        ull sb = (m & 2) ? B[j] : B[j + 2];
        ull ca = __shfl_xor_sync(0xffffffffu, sa, 2);
        ull cb = __shfl_xor_sync(0xffffffffu, sb, 2);
        A[j] = add2((m & 2) ? A[j + 2] : A[j], ca);
        B[j] = add2((m & 2) ? B[j + 2] : B[j], cb);
    }
    {
        ull sa = (m & 1) ? A[0] : A[1];
        ull sb = (m & 1) ? B[0] : B[1];
        ull ca = __shfl_xor_sync(0xffffffffu, sa, 1);
        ull cb = __shfl_xor_sync(0xffffffffu, sb, 1);
        A[0] = add2((m & 1) ? A[1] : A[0], ca);
        B[0] = add2((m & 1) ? B[1] : B[0], cb);
    }
}

__device__ __forceinline__ void butterfly16(ull A[16], int m)
{
    #pragma unroll
    for (int j = 0; j < 8; j++) {
        ull s = (m & 8) ? A[j] : A[j + 8];
        ull c = __shfl_xor_sync(0xffffffffu, s, 8);
        A[j] = add2((m & 8) ? A[j + 8] : A[j], c);
    }
    #pragma unroll
    for (int j = 0; j < 4; j++) {
        ull s = (m & 4) ? A[j] : A[j + 4];
        ull c = __shfl_xor_sync(0xffffffffu, s, 4);
        A[j] = add2((m & 4) ? A[j + 4] : A[j], c);
    }
    #pragma unroll
    for (int j = 0; j < 2; j++) {
        ull s = (m & 2) ? A[j] : A[j + 2];
        ull c = __shfl_xor_sync(0xffffffffu, s, 2);
        A[j] = add2((m & 2) ? A[j + 2] : A[j], c);
    }
    {
        ull s = (m & 1) ? A[0] : A[1];
        ull c = __shfl_xor_sync(0xffffffffu, s, 1);
        A[0] = add2((m & 1) ? A[1] : A[0], c);
    }
}

__device__ __forceinline__ void grid_barrier(int t)
{
    __threadfence();
    __syncthreads();
    if (t == 0) {
        unsigned s0 = *((volatile unsigned*)&g_sense);
        unsigned old = atomicAdd(&g_count, 1u);
        if (old == (unsigned)(gridDim.x - 1)) {
            atomicExch(&g_count, 0u);
            __threadfence();
            atomicAdd(&g_sense, 1u);
        } else {
            while (*((volatile unsigned*)&g_sense) == s0) { }
        }
    }
    __syncthreads();
}

__device__ __forceinline__ void cpasync16(uint dst, const float* src)
{
    asm volatile("cp.async.ca.shared.global [%0], [%1], 16;"
                 :: "r"(dst), "l"(src) : "memory");
}

// ===========================================================================
// MONO2: phase0 (xs stage + xT transpose + tau + cp.async weights) ->
//        grid barrier -> sort column b (coalesced xT) -> grid barrier ->
//        fused tail (mv1/mv3 interleave from smem weights, mv2, LN).
// 128 blocks x 512 threads, all co-resident.
// ===========================================================================
__global__ __launch_bounds__(512) void mono2_kernel(
    const float* __restrict__ x,
    const float* __restrict__ Wd, const float* __restrict__ bd,
    const float* __restrict__ Wt, const float* __restrict__ bt,
    const float* __restrict__ Wa, const float* __restrict__ ba,
    const float* __restrict__ Wr, const float* __restrict__ br,
    const float* __restrict__ gamma, const float* __restrict__ beta,
    float* __restrict__ xT, float* __restrict__ dmT,
    float* __restrict__ out)
{
    extern __shared__ __align__(16) float smem[];
    float* Wd_s = smem + OFF_W;
    float* Wa_s = smem + OFF_W + 16384;
    float* Wr_s = smem + OFF_W + 32768;
    float* xs   = smem + OFF_XS;
    uint*  sv   = (uint*)(smem + OFF_UN);      // sort phase
    float* ps   = smem + OFF_UN + 1024;        // sort phase
    float* ds   = smem + OFF_UN;               // tail phase (aliased)
    float* hs   = smem + OFF_UN + 1088;        // tail phase (aliased)
    float* cb   = smem + OFF_CB;               // Wt|bd|ba|br|g|be
    float* redS = smem + OFF_RED;
    float* redQ = smem + OFF_RED + 128;
    float* wsum = smem + OFF_WSUM;
    float* rtau_s = smem + OFF_RTAU;
    float* musig  = smem + OFF_MS;

    const int b = blockIdx.x;
    const int t = threadIdx.x;
    const int lane = t & 31;
    const int i0 = b * 8;

    // =====================================================================
    // PHASE 0a: cp.async all three weight tiles (thread-private, CF layout)
    // =====================================================================
    {
        const int colbase = (t >> 4) * 4;
        const int k0 = (t & 15) * 8;
        const float* mats[3] = { Wd, Wa, Wr };
        #pragma unroll
        for (int mi = 0; mi < 3; mi++) {
            uint dbase = (uint)__cvta_generic_to_shared(smem + OFF_W + mi * 16384);
            #pragma unroll
            for (int j = 0; j < 8; j++) {
                int c = j >> 1, half = j & 1;
                const float* src = mats[mi] + (colbase + c) * DN + k0 + half * 4;
                uint dst = dbase + (uint)(((j * 512 + t) << 2) * 4);
                cpasync16(dst, src);
            }
        }
        asm volatile("cp.async.commit_group;" ::: "memory");
    }

    // =====================================================================
    // PHASE 0b: stage xs, small vectors; transpose to xT; compute rtau
    // =====================================================================
    #pragma unroll
    for (int it = 0; it < 2; it++) {
        int e = t + it * 512;
        int r = e >> 7, k = e & 127;
        xs[IDX(k, r)] = x[(i0 + r) * DN + k];
    }
    if (t < 128)       { cb[t] = Wt[t];              cb[512 + t] = gamma[t]; }
    else if (t < 256)  { cb[t] = bd[t - 128];        cb[512 + t] = beta[t - 128]; }
    else if (t < 384)  { cb[t] = ba[t - 256]; }
    else               { cb[t] = br[t - 384]; }
    __syncthreads();

    // transposed write xT[d][i0+r]
    #pragma unroll
    for (int it = 0; it < 2; it++) {
        int e = t + it * 512;
        int d = e >> 3, r = e & 7;
        xT[d * BN + i0 + r] = xs[IDX(d, r)];
    }

    // tau partials (threads 0..127 = 128 k's)
    if (t < 128) {
        int o = IDX(t, 0);
        float4 xa = *(const float4*)(xs + o);
        float4 xb = *(const float4*)(xs + o + 4);
        float wt = cb[t];
        float pr[8] = { xa.x * wt, xa.y * wt, xa.z * wt, xa.w * wt,
                        xb.x * wt, xb.y * wt, xb.z * wt, xb.w * wt };
        #pragma unroll
        for (int r = 0; r < 8; r++) {
            float v = pr[r];
            #pragma unroll
            for (int o2 = 16; o2; o2 >>= 1) v += __shfl_xor_sync(0xffffffffu, v, o2);
            if (lane == 0) redS[(t >> 5) * 8 + r] = v;
        }
    }
    __syncthreads();
    if (t < 8) {
        float z = redS[t] + redS[8 + t] + redS[16 + t] + redS[24 + t] + bt[0];
        float sp = fmaxf(z, 0.0f) + log1pf(expf(-fabsf(z)));
        rtau_s[t] = 1.0f / (fmaxf(sp, 0.01f) + 1.0f);
    }

    // =====================================================================
    // GRID BARRIER 1: xT complete
    // =====================================================================
    grid_barrier(t);

    // =====================================================================
    // PHASE 1: sort column d = b (coalesced xT reads), write dmT[b][*]
    // =====================================================================
    {
        const int d = b;
        const int w = t >> 5;
        const int p0 = (w << 6) + lane;
        const int p1 = p0 + 32;

        const float f0 = xT[d * BN + p0];
        const float f1 = xT[d * BN + p1];
        const uint e0 = encf(f0);
        const uint e1 = encf(f1);
        uint r0 = e0, r1 = e1;

        #pragma unroll
        for (int k = 2; k <= 64; k <<= 1) {
            #pragma unroll
            for (int j = k >> 1; j > 0; j >>= 1) {
                if (j == 32) {
                    bool up = ((p0 & k) == 0);
                    uint lo = min(r0, r1), hi = max(r0, r1);
                    r0 = up ? lo : hi;
                    r1 = up ? hi : lo;
                } else {
                    bool up0 = ((p0 & k) == 0);
                    bool km0 = (((p0 & j) == 0) == up0);
                    uint o0 = __shfl_xor_sync(0xffffffffu, r0, j);
                    r0 = km0 ? min(r0, o0) : max(r0, o0);
                    bool up1 = ((p1 & k) == 0);
                    bool km1 = (((p1 & j) == 0) == up1);
                    uint o1 = __shfl_xor_sync(0xffffffffu, r1, j);
                    r1 = km1 ? min(r1, o1) : max(r1, o1);
                }
            }
        }

        sv[p0] = r0; sv[p1] = r1;
        g64(t);
        sstage<128, 64>(sv, t);
        g64(t);
        r0 = sv[p0]; r1 = sv[p1];
        rtail(r0, r1, p0, (p0 & 128) == 0);

        sv[p0] = r0; sv[p1] = r1;
        g128(t);
        sstage<256, 128>(sv, t);
        g128(t);
        sstage<256, 64>(sv, t);
        g64(t);
        r0 = sv[p0]; r1 = sv[p1];
        rtail(r0, r1, p0, (p0 & 256) == 0);

        sv[p0] = r0; sv[p1] = r1;
        g256(t);
        sstage<512, 256>(sv, t);
        g256(t);
        sstage<512, 128>(sv, t);
        g128(t);
        sstage<512, 64>(sv, t);
        g64(t);
        r0 = sv[p0]; r1 = sv[p1];
        rtail(r0, r1, p0, (p0 & 512) == 0);

        sv[p0] = r0; sv[p1] = r1;
        __syncthreads();
        sstage<1024, 512>(sv, t);
        __syncthreads();
        sstage<1024, 256>(sv, t);
        g256(t);
        sstage<1024, 128>(sv, t);
        g128(t);
        sstage<1024, 64>(sv, t);
        g64(t);
        r0 = sv[p0]; r1 = sv[p1];
        rtail(r0, r1, p0, true);

        sv[p0] = r0;
        sv[p1] = r1;
        float v0 = decf(r0);
        float v1 = decf(r1);

        float s0 = v0;
        #pragma unroll
        for (int o = 1; o < 32; o <<= 1) {
            float n = __shfl_up_sync(0xffffffffu, s0, o);
            if (lane >= o) s0 += n;
        }
        float T0 = __shfl_sync(0xffffffffu, s0, 31);
        float s1 = v1;
        #pragma unroll
        for (int o = 1; o < 32; o <<= 1) {
            float n = __shfl_up_sync(0xffffffffu, s1, o);
            if (lane >= o) s1 += n;
        }
        float T1 = __shfl_sync(0xffffffffu, s1, 31);
        if (lane == 0) wsum[w] = T0 + T1;
        __syncthreads();
        if (t < 16) {
            float v = wsum[t];
            #pragma unroll
            for (int o = 1; o < 16; o <<= 1) {
                float n = __shfl_up_sync(0x0000ffffu, v, o);
                if (t >= o) v += n;
            }
            wsum[t] = v;
        }
        __syncthreads();
        const float S = wsum[15];
        const float wexcl = (w == 0) ? 0.0f : wsum[w - 1];
        ps[p0] = wexcl + s0;
        ps[p1] = wexcl + T0 + s1;
        __syncthreads();

        {
            int q = 0;
            #pragma unroll
            for (int st = 512; st > 0; st >>= 1) {
                int nq = q + st;
                if (sv[nq - 1] < e0) q = nq;
            }
            float o = f0 * (float)(2 * (q + 1) - BN) + S - 2.0f * ps[q];
            dmT[d * BN + p0] = o * (1.0f / (float)BN);
        }
        {
            int q = 0;
            #pragma unroll
            for (int st = 512; st > 0; st >>= 1) {
                int nq = q + st;
                if (sv[nq - 1] < e1) q = nq;
            }
            float o = f1 * (float)(2 * (q + 1) - BN) + S - 2.0f * ps[q];
            dmT[d * BN + p1] = o * (1.0f / (float)BN);
        }
    }

    // =====================================================================
    // GRID BARRIER 2: dmT complete
    // =====================================================================
    grid_barrier(t);

    // =====================================================================
    // PHASE 2: fused tail (weights from smem; xs + rtau_s from phase 0)
    // =====================================================================
    const int m = lane & 15;
    const int colbase = (t >> 4) * 4;
    const int col = colbase + (m >> 2);
    const int r0p = 2 * (m & 3);

    // stage ds from dmT (sv/ps dead now)
    #pragma unroll
    for (int it = 0; it < 2; it++) {
        int e = t + it * 512;
        int k = e >> 3, r = e & 7;
        ds[IDX(k, r)] = dmT[k * BN + i0 + r];
    }
    asm volatile("cp.async.wait_group 0;" ::: "memory");   // own weights ready
    __syncthreads();                                        // ds ready

    ull A1[16], A3[16];
    #pragma unroll
    for (int i = 0; i < 16; i++) { A1[i] = 0ull; A3[i] = 0ull; }

    const float* dsp = ds + m * CHW;
    const float* xsp = xs + m * CHW;

    float4 wd[4], wr[4];
    lw4s(Wd_s, t, 0, wd);
    lw4s(Wr_s, t, 0, wr);
    mv_acc4(dsp, 0, wd, A1);
    mv_acc4(xsp, 0, wr, A3);
    lw4s(Wd_s, t, 1, wd);
    lw4s(Wr_s, t, 1, wr);
    mv_acc4(dsp, 4, wd, A1);
    mv_acc4(xsp, 4, wr, A3);

    butterfly16x2(A1, A3, m);
    float s1a = __uint_as_float((uint)A1[0]);
    float s1b = __uint_as_float((uint)(A1[0] >> 32));
    float s3a = __uint_as_float((uint)A3[0]);
    float s3b = __uint_as_float((uint)(A3[0] >> 32));

    {
        float bdv = cb[128 + col];
        float hm0 = (s1a + bdv) * rtau_s[r0p];
        float hm1 = (s1b + bdv) * rtau_s[r0p + 1];
        *(float2*)(hs + IDX(col, r0p)) = make_float2(hm0, hm1);
    }
    __syncthreads();                        // hs ready

    #pragma unroll
    for (int i = 0; i < 16; i++) A1[i] = 0ull;
    const float* hsp = hs + m * CHW;
    float4 wa[4];
    lw4s(Wa_s, t, 0, wa);
    mv_acc4(hsp, 0, wa, A1);
    lw4s(Wa_s, t, 1, wa);
    mv_acc4(hsp, 4, wa, A1);
    butterfly16(A1, m);
    float s2a = __uint_as_float((uint)A1[0]);
    float s2b = __uint_as_float((uint)(A1[0] >> 32));

    float bav = cb[256 + col], brv = cb[384 + col];
    float y0 = fmaxf(s2a + bav, 0.0f) + s3a + brv;
    float y1 = fmaxf(s2b + bav, 0.0f) + s3b + brv;

    // LayerNorm
    float sa = y0, qa = y0 * y0, sb2 = y1, qb2 = y1 * y1;
    #pragma unroll
    for (int mk = 4; mk <= 16; mk <<= 1) {
        sa  += __shfl_xor_sync(0xffffffffu, sa, mk);
        qa  += __shfl_xor_sync(0xffffffffu, qa, mk);
        sb2 += __shfl_xor_sync(0xffffffffu, sb2, mk);
        qb2 += __shfl_xor_sync(0xffffffffu, qb2, mk);
    }
    if (lane < 4) {
        int wp = t >> 5;
        redS[wp * 8 + r0p] = sa;      redQ[wp * 8 + r0p] = qa;
        redS[wp * 8 + r0p + 1] = sb2; redQ[wp * 8 + r0p + 1] = qb2;
    }
    __syncthreads();
    if (t < 8) {
        float ss = 0.0f, qs = 0.0f;
        #pragma unroll
        for (int wp = 0; wp < 16; wp++) { ss += redS[wp * 8 + t]; qs += redQ[wp * 8 + t]; }
        float mu = ss * (1.0f / 128.0f);
        float var = qs * (1.0f / 128.0f) - mu * mu;
        musig[2 * t] = mu;
        musig[2 * t + 1] = rsqrtf(var + LN_EPS);
    }
    __syncthreads();
    float gv = cb[512 + col], bv = cb[640 + col];
    out[(i0 + r0p) * HN + col]     = (y0 - musig[2 * r0p]) * musig[2 * r0p + 1] * gv + bv;
    out[(i0 + r0p + 1) * HN + col] = (y1 - musig[2 * r0p + 2]) * musig[2 * r0p + 3] * gv + bv;
}

// ===========================================================================
extern "C" void kernel_launch(void* const* d_in, const int* in_sizes, int n_in,
                              void* d_out, int out_size)
{
    const float* x     = (const float*)d_in[0];
    const float* Wd    = (const float*)d_in[1];
    const float* bd    = (const float*)d_in[2];
    const float* Wt    = (const float*)d_in[3];
    const float* bt    = (const float*)d_in[4];
    const float* Wa    = (const float*)d_in[5];
    const float* ba    = (const float*)d_in[6];
    const float* Wr    = (const float*)d_in[7];
    const float* br    = (const float*)d_in[8];
    const float* gamma = (const float*)d_in[9];
    const float* beta  = (const float*)d_in[10];
    float* out = (float*)d_out;

    float *dmT = nullptr, *xT = nullptr;
    cudaGetSymbolAddress((void**)&dmT, g_dmT);
    cudaGetSymbolAddress((void**)&xT, g_xT);

    static bool attr_set = false;
    if (!attr_set) {
        cudaFuncSetAttribute(mono2_kernel,
                             cudaFuncAttributeMaxDynamicSharedMemorySize,
                             SMEM_BYTES);
        attr_set = true;
    }

    mono2_kernel<<<DN, 512, SMEM_BYTES>>>(
        x, Wd, bd, Wt, bt, Wa, ba, Wr, br, gamma, beta, xT, dmT, out);
}

// round 14
// speedup vs baseline: 1.0050x; 1.0050x over previous
#include <cuda_runtime.h>
#include <math.h>

#define BN 1024
#define DN 128
#define HN 128
#define LN_EPS 1e-5f

__device__ float g_dmT[DN * BN];    // [d][i]

typedef unsigned long long ull;
typedef unsigned int uint;

// ===========================================================================
// order-preserving float <-> uint encode
// ===========================================================================
__device__ __forceinline__ uint encf(float f) {
    uint u = __float_as_uint(f);
    return u ^ ((u & 0x80000000u) ? 0xFFFFFFFFu : 0x80000000u);
}
__device__ __forceinline__ float decf(uint u) {
    u ^= (u & 0x80000000u) ? 0x80000000u : 0xFFFFFFFFu;
    return __uint_as_float(u);
}

// ===========================================================================
// K1 (paired): 64 CTAs x 1024 threads; threads 0-511 sort column 2b,
// threads 512-1023 sort column 2b+1 — two INDEPENDENT barrier chains per
// SM hide each other's latency. Named barriers (g128/g256/g512) use
// disjoint ids per group; no cross-half sync anywhere.
// ===========================================================================
__device__ __forceinline__ void b128(int t) {
    asm volatile("bar.sync %0, 128;" :: "r"(t >> 7) : "memory");        // 0-7
}
__device__ __forceinline__ void b256(int t) {
    asm volatile("bar.sync %0, 256;" :: "r"(8 + (t >> 8)) : "memory");  // 8-11
}
__device__ __forceinline__ void b512(int t) {
    asm volatile("bar.sync %0, 512;" :: "r"(12 + (t >> 9)) : "memory"); // 12-13
}

template<int K, int J>
__device__ __forceinline__ void sstage(uint* __restrict__ sv, int th) {
    int i = ((th & ~(J - 1)) << 1) | (th & (J - 1));
    int ixj = i | J;
    uint a = sv[i];
    uint b = sv[ixj];
    if ((a > b) == ((i & K) == 0)) { sv[i] = b; sv[ixj] = a; }
}

__device__ __forceinline__ void rtail(uint& r0, uint& r1, int p0, bool up) {
    uint lo = min(r0, r1), hi = max(r0, r1);
    r0 = up ? lo : hi;
    r1 = up ? hi : lo;
    #pragma unroll
    for (int j = 16; j > 0; j >>= 1) {
        bool km = (((p0 & j) == 0) == up);
        uint o0 = __shfl_xor_sync(0xffffffffu, r0, j);
        r0 = km ? min(r0, o0) : max(r0, o0);
        uint o1 = __shfl_xor_sync(0xffffffffu, r1, j);
        r1 = km ? min(r1, o1) : max(r1, o1);
    }
}

__global__ __launch_bounds__(1024) void sort2_kernel(
    const float* __restrict__ x, float* __restrict__ dmT)
{
    __shared__ uint  sv2[2][BN];
    __shared__ float ps2[2][BN];
    __shared__ float wsum2[2][16];

    const int t = threadIdx.x;
    const int h = t >> 9;            // half (independent sort instance)
    const int th = t & 511;
    const int d = blockIdx.x * 2 + h;
    const int lane = t & 31;
    const int w = th >> 5;
    const int p0 = (w << 6) + lane;
    const int p1 = p0 + 32;

    uint*  sv = sv2[h];
    float* ps = ps2[h];
    float* wsum = wsum2[h];

    const float f0 = x[p0 * DN + d];
    const float f1 = x[p1 * DN + d];
    const uint e0 = encf(f0);
    const uint e1 = encf(f1);
    uint r0 = e0, r1 = e1;

    // ---- phase A: k = 2..64, registers/shfl only (warp-local) ----
    #pragma unroll
    for (int k = 2; k <= 64; k <<= 1) {
        #pragma unroll
        for (int j = k >> 1; j > 0; j >>= 1) {
            if (j == 32) {
                bool up = ((p0 & k) == 0);
                uint lo = min(r0, r1), hi = max(r0, r1);
                r0 = up ? lo : hi;
                r1 = up ? hi : lo;
            } else {
                bool up0 = ((p0 & k) == 0);
                bool km0 = (((p0 & j) == 0) == up0);
                uint o0 = __shfl_xor_sync(0xffffffffu, r0, j);
                r0 = km0 ? min(r0, o0) : max(r0, o0);
                bool up1 = ((p1 & k) == 0);
                bool km1 = (((p1 & j) == 0) == up1);
                uint o1 = __shfl_xor_sync(0xffffffffu, r1, j);
                r1 = km1 ? min(r1, o1) : max(r1, o1);
            }
        }
    }

    // ---- phase B: smem stages, half-scoped grouped barriers ----
    // k = 128
    sv[p0] = r0; sv[p1] = r1;
    b128(t);
    sstage<128, 64>(sv, th);
    b128(t);
    r0 = sv[p0]; r1 = sv[p1];
    rtail(r0, r1, p0, (p0 & 128) == 0);

    // k = 256
    sv[p0] = r0; sv[p1] = r1;
    b128(t);
    sstage<256, 128>(sv, th);
    b128(t);
    sstage<256, 64>(sv, th);
    b128(t);
    r0 = sv[p0]; r1 = sv[p1];
    rtail(r0, r1, p0, (p0 & 256) == 0);

    // k = 512
    sv[p0] = r0; sv[p1] = r1;
    b256(t);
    sstage<512, 256>(sv, th);
    b256(t);
    sstage<512, 128>(sv, th);
    b128(t);
    sstage<512, 64>(sv, th);
    b128(t);
    r0 = sv[p0]; r1 = sv[p1];
    rtail(r0, r1, p0, (p0 & 512) == 0);

    // k = 1024
    sv[p0] = r0; sv[p1] = r1;
    b512(t);
    sstage<1024, 512>(sv, th);
    b512(t);
    sstage<1024, 256>(sv, th);
    b256(t);
    sstage<1024, 128>(sv, th);
    b128(t);
    sstage<1024, 64>(sv, th);
    b128(t);
    r0 = sv[p0]; r1 = sv[p1];
    rtail(r0, r1, p0, true);

    // ---- sorted keys + prefix sums ----
    sv[p0] = r0;
    sv[p1] = r1;
    float v0 = decf(r0);
    float v1 = decf(r1);

    float s0 = v0;
    #pragma unroll
    for (int o = 1; o < 32; o <<= 1) {
        float n = __shfl_up_sync(0xffffffffu, s0, o);
        if (lane >= o) s0 += n;
    }
    float T0 = __shfl_sync(0xffffffffu, s0, 31);
    float s1 = v1;
    #pragma unroll
    for (int o = 1; o < 32; o <<= 1) {
        float n = __shfl_up_sync(0xffffffffu, s1, o);
        if (lane >= o) s1 += n;
    }
    float T1 = __shfl_sync(0xffffffffu, s1, 31);
    if (lane == 0) wsum[w] = T0 + T1;
    b512(t);
    if (th < 16) {
        float v = wsum[th];
        #pragma unroll
        for (int o = 1; o < 16; o <<= 1) {
            float n = __shfl_up_sync(0x0000ffffu, v, o);
            if (th >= o) v += n;
        }
        wsum[th] = v;
    }
    b512(t);
    const float S = wsum[15];
    const float wexcl = (w == 0) ? 0.0f : wsum[w - 1];
    ps[p0] = wexcl + s0;
    ps[p1] = wexcl + T0 + s1;
    b512(t);

    // ---- binary-search ranks of original elements; coalesced writes ----
    {
        int q = 0;
        #pragma unroll
        for (int st = 512; st > 0; st >>= 1) {
            int nq = q + st;
            if (sv[nq - 1] < e0) q = nq;
        }
        float o = f0 * (float)(2 * (q + 1) - BN) + S - 2.0f * ps[q];
        dmT[d * BN + p0] = o * (1.0f / (float)BN);
    }
    {
        int q = 0;
        #pragma unroll
        for (int st = 512; st > 0; st >>= 1) {
            int nq = q + st;
            if (sv[nq - 1] < e1) q = nq;
        }
        float o = f1 * (float)(2 * (q + 1) - BN) + S - 2.0f * ps[q];
        dmT[d * BN + p1] = o * (1.0f / (float)BN);
    }
}

// ===========================================================================
// tail (R12-verbatim, measured 9.44us): 128 blocks x 8 rows, 512 threads.
// ===========================================================================
__device__ __forceinline__ ull fma2(ull a, ull b, ull c) {
    ull d;
    asm("fma.rn.f32x2 %0, %1, %2, %3;" : "=l"(d) : "l"(a), "l"(b), "l"(c));
    return d;
}
__device__ __forceinline__ ull add2(ull a, ull b) {
    ull d;
    asm("add.rn.f32x2 %0, %1, %2;" : "=l"(d) : "l"(a), "l"(b));
    return d;
}
__device__ __forceinline__ ull dup2(float w) {
    ull d;
    asm("mov.b64 %0, {%1, %1};" : "=l"(d) : "r"(__float_as_uint(w)));
    return d;
}

#define CHW 68
#define IDX(k, r) ((((k) >> 3) * CHW) + (((k) & 7) << 3) + (r))

__device__ __forceinline__ void load_w4(const float* __restrict__ W,
                                        int colbase, int k0, float4 wv[4])
{
    #pragma unroll
    for (int c = 0; c < 4; c++)
        wv[c] = *(const float4*)(W + (colbase + c) * DN + k0);
}

__device__ __forceinline__ void mv_acc4(const float* __restrict__ ip, int kb,
                                        const float4 wv[4], ull A[16])
{
    #pragma unroll
    for (int kl = 0; kl < 4; kl++) {
        ulonglong2 q0 = *(const ulonglong2*)(ip + (kb + kl) * 8);
        ulonglong2 q1 = *(const ulonglong2*)(ip + (kb + kl) * 8 + 4);
        #pragma unroll
        for (int c = 0; c < 4; c++) {
            ull w2 = dup2(((const float*)&wv[c])[kl]);
            A[c * 4 + 0] = fma2(q0.x, w2, A[c * 4 + 0]);
            A[c * 4 + 1] = fma2(q0.y, w2, A[c * 4 + 1]);
            A[c * 4 + 2] = fma2(q1.x, w2, A[c * 4 + 2]);
            A[c * 4 + 3] = fma2(q1.y, w2, A[c * 4 + 3]);
        }
    }
}

__device__ __forceinline__ void butterfly16x2(ull A[16], ull B[16], int m)
{
    #pragma unroll
    for (int j = 0; j < 8; j++) {
        ull sa = (m & 8) ? A[j] : A[j + 8];
        ull sb = (m & 8) ? B[j] : B[j + 8];
        ull ca = __shfl_xor_sync(0xffffffffu, sa, 8);
        ull cb = __shfl_xor_sync(0xffffffffu, sb, 8);
        A[j] = add2((m & 8) ? A[j + 8] : A[j], ca);
        B[j] = add2((m & 8) ? B[j + 8] : B[j], cb);
    }
    #pragma unroll
    for (int j = 0; j < 4; j++) {
        ull sa = (m & 4) ? A[j] : A[j + 4];
        ull sb = (m & 4) ? B[j] : B[j + 4];
        ull ca = __shfl_xor_sync(0xffffffffu, sa, 4);
        ull cb = __shfl_xor_sync(0xffffffffu, sb, 4);
        A[j] = add2((m & 4) ? A[j + 4] : A[j], ca);
        B[j] = add2((m & 4) ? B[j + 4] : B[j], cb);
    }
    #pragma unroll
    for (int j = 0; j < 2; j++) {
        ull sa = (m & 2) ? A[j] : A[j + 2];
        ull sb = (m & 2) ? B[j] : B[j + 2];
        ull ca = __shfl_xor_sync(0xffffffffu, sa, 2);
        ull cb = __shfl_xor_sync(0xffffffffu, sb, 2);
        A[j] = add2((m & 2) ? A[j + 2] : A[j], ca);
        B[j] = add2((m & 2) ? B[j + 2] : B[j], cb);
    }
    {
        ull sa = (m & 1) ? A[0] : A[1];
        ull sb = (m & 1) ? B[0] : B[1];
        ull ca = __shfl_xor_sync(0xffffffffu, sa, 1);
        ull cb = __shfl_xor_sync(0xffffffffu, sb, 1);
        A[0] = add2((m & 1) ? A[1] : A[0], ca);
        B[0] = add2((m & 1) ? B[1] : B[0], cb);
    }
}

__device__ __forceinline__ void butterfly16(ull A[16], int m)
{
    #pragma unroll
    for (int j = 0; j < 8; j++) {
        ull s = (m & 8) ? A[j] : A[j + 8];
        ull c = __shfl_xor_sync(0xffffffffu, s, 8);
        A[j] = add2((m & 8) ? A[j + 8] : A[j], c);
    }
    #pragma unroll
    for (int j = 0; j < 4; j++) {
        ull s = (m & 4) ? A[j] : A[j + 4];
        ull c = __shfl_xor_sync(0xffffffffu, s, 4);
        A[j] = add2((m & 4) ? A[j + 4] : A[j], c);
    }
    #pragma unroll
    for (int j = 0; j < 2; j++) {
        ull s = (m & 2) ? A[j] : A[j + 2];
        ull c = __shfl_xor_sync(0xffffffffu, s, 2);
        A[j] = add2((m & 2) ? A[j + 2] : A[j], c);
    }
    {
        ull s = (m & 1) ? A[0] : A[1];
        ull c = __shfl_xor_sync(0xffffffffu, s, 1);
        A[0] = add2((m & 1) ? A[1] : A[0], c);
    }
}

__global__ __launch_bounds__(512) void tail_kernel(
    const float* __restrict__ x,
    const float* __restrict__ Wd, const float* __restrict__ bd,
    const float* __restrict__ Wt, const float* __restrict__ bt,
    const float* __restrict__ Wa, const float* __restrict__ ba,
    const float* __restrict__ Wr, const float* __restrict__ br,
    const float* __restrict__ gamma, const float* __restrict__ beta,
    const float* __restrict__ dmT, float* __restrict__ out)
{
    __shared__ __align__(16) float xs[16 * CHW];
    __shared__ __align__(16) float ds[16 * CHW];
    __shared__ __align__(16) float hs[16 * CHW];
    __shared__ float Wt_s[128], bd_s[128], ba_s[128], br_s[128], g_s[128], be_s[128];
    __shared__ float redS[128], redQ[128];
    __shared__ float rtau_s[8];
    __shared__ float musig[16];

    const int t = threadIdx.x;
    const int lane = t & 31;
    const int m = lane & 15;
    const int colbase = (t >> 4) * 4;
    const int k0 = m * 8;
    const int i0 = blockIdx.x * 8;
    const int col = colbase + (m >> 2);
    const int r0 = 2 * (m & 3);

    float4 wd[4], wr[4];
    load_w4(Wd, colbase, k0, wd);
    load_w4(Wr, colbase, k0, wr);

    #pragma unroll
    for (int it = 0; it < 2; it++) {
        int e = t + it * 512;
        int r = e >> 7, k = e & 127;
        xs[IDX(k, r)] = x[(i0 + r) * DN + k];
    }
    #pragma unroll
    for (int it = 0; it < 2; it++) {
        int e = t + it * 512;
        int k = e >> 3, r = e & 7;
        ds[IDX(k, r)] = dmT[k * BN + i0 + r];
    }
    if (t < 128)       { Wt_s[t] = Wt[t];             g_s[t] = gamma[t]; }
    else if (t < 256)  { bd_s[t - 128] = bd[t - 128]; be_s[t - 128] = beta[t - 128]; }
    else if (t < 384)  { ba_s[t - 256] = ba[t - 256]; }
    else               { br_s[t - 384] = br[t - 384]; }
    __syncthreads();

    if (t < 128) {
        int o = IDX(t, 0);
        float4 xa = *(const float4*)(xs + o);
        float4 xb = *(const float4*)(xs + o + 4);
        float wt = Wt_s[t];
        float pr[8] = { xa.x * wt, xa.y * wt, xa.z * wt, xa.w * wt,
                        xb.x * wt, xb.y * wt, xb.z * wt, xb.w * wt };
        #pragma unroll
        for (int r = 0; r < 8; r++) {
            float v = pr[r];
            #pragma unroll
            for (int o2 = 16; o2; o2 >>= 1) v += __shfl_xor_sync(0xffffffffu, v, o2);
            if (lane == 0) redS[(t >> 5) * 8 + r] = v;
        }
    }
    __syncthreads();
    if (t < 8) {
        float z = redS[t] + redS[8 + t] + redS[16 + t] + redS[24 + t] + bt[0];
        float sp = fmaxf(z, 0.0f) + log1pf(expf(-fabsf(z)));
        rtau_s[t] = 1.0f / (fmaxf(sp, 0.01f) + 1.0f);
    }

    ull A1[16], A3[16];
    #pragma unroll
    for (int i = 0; i < 16; i++) { A1[i] = 0ull; A3[i] = 0ull; }

    const float* dsp = ds + m * CHW;
    const float* xsp = xs + m * CHW;

    mv_acc4(dsp, 0, wd, A1);
    mv_acc4(xsp, 0, wr, A3);
    load_w4(Wd, colbase, k0 + 4, wd);
    load_w4(Wr, colbase, k0 + 4, wr);
    mv_acc4(dsp, 4, wd, A1);
    mv_acc4(xsp, 4, wr, A3);

    butterfly16x2(A1, A3, m);
    float s1a = __uint_as_float((uint)A1[0]);
    float s1b = __uint_as_float((uint)(A1[0] >> 32));
    float s3a = __uint_as_float((uint)A3[0]);
    float s3b = __uint_as_float((uint)(A3[0] >> 32));

    __syncthreads();
    {
        float bdv = bd_s[col];
        float hm0 = (s1a + bdv) * rtau_s[r0];
        float hm1 = (s1b + bdv) * rtau_s[r0 + 1];
        *(float2*)(hs + IDX(col, r0)) = make_float2(hm0, hm1);
    }
    float4 wa[4], wa2[4];
    load_w4(Wa, colbase, k0, wa);
    load_w4(Wa, colbase, k0 + 4, wa2);
    __syncthreads();

    #pragma unroll
    for (int i = 0; i < 16; i++) A1[i] = 0ull;
    const float* hsp = hs + m * CHW;
    mv_acc4(hsp, 0, wa, A1);
    mv_acc4(hsp, 4, wa2, A1);
    butterfly16(A1, m);
    float s2a = __uint_as_float((uint)A1[0]);
    float s2b = __uint_as_float((uint)(A1[0] >> 32));

    float bav = ba_s[col], brv = br_s[col];
    float y0 = fmaxf(s2a + bav, 0.0f) + s3a + brv;
    float y1 = fmaxf(s2b + bav, 0.0f) + s3b + brv;

    float sa = y0, qa = y0 * y0, sb2 = y1, qb2 = y1 * y1;
    #pragma unroll
    for (int mk = 4; mk <= 16; mk <<= 1) {
        sa  += __shfl_xor_sync(0xffffffffu, sa, mk);
        qa  += __shfl_xor_sync(0xffffffffu, qa, mk);
        sb2 += __shfl_xor_sync(0xffffffffu, sb2, mk);
        qb2 += __shfl_xor_sync(0xffffffffu, qb2, mk);
    }
    if (lane < 4) {
        int wp = t >> 5;
        redS[wp * 8 + r0] = sa;      redQ[wp * 8 + r0] = qa;
        redS[wp * 8 + r0 + 1] = sb2; redQ[wp * 8 + r0 + 1] = qb2;
    }
    __syncthreads();
    if (t < 8) {
        float ss = 0.0f, qs = 0.0f;
        #pragma unroll
        for (int wp = 0; wp < 16; wp++) { ss += redS[wp * 8 + t]; qs += redQ[wp * 8 + t]; }
        float mu = ss * (1.0f / 128.0f);
        float var = qs * (1.0f / 128.0f) - mu * mu;
        musig[2 * t] = mu;
        musig[2 * t + 1] = rsqrtf(var + LN_EPS);
    }
    __syncthreads();
    float gv = g_s[col], bv = be_s[col];
    out[(i0 + r0) * HN + col]     = (y0 - musig[2 * r0]) * musig[2 * r0 + 1] * gv + bv;
    out[(i0 + r0 + 1) * HN + col] = (y1 - musig[2 * r0 + 2]) * musig[2 * r0 + 3] * gv + bv;
}

// ===========================================================================
extern "C" void kernel_launch(void* const* d_in, const int* in_sizes, int n_in,
                              void* d_out, int out_size)
{
    const float* x     = (const float*)d_in[0];
    const float* Wd    = (const float*)d_in[1];
    const float* bd    = (const float*)d_in[2];
    const float* Wt    = (const float*)d_in[3];
    const float* bt    = (const float*)d_in[4];
    const float* Wa    = (const float*)d_in[5];
    const float* ba    = (const float*)d_in[6];
    const float* Wr    = (const float*)d_in[7];
    const float* br    = (const float*)d_in[8];
    const float* gamma = (const float*)d_in[9];
    const float* beta  = (const float*)d_in[10];
    float* out = (float*)d_out;

    float* dmT = nullptr;
    cudaGetSymbolAddress((void**)&dmT, g_dmT);

    sort2_kernel<<<DN / 2, 1024>>>(x, dmT);
    tail_kernel<<<BN / 8, 512>>>(
        x, Wd, bd, Wt, bt, Wa, ba, Wr, br, gamma, beta, dmT, out);
}

// round 16
// speedup vs baseline: 1.1234x; 1.1178x over previous
#include <cuda_runtime.h>
#include <math.h>

#define BN 1024
#define DN 128
#define HN 128
#define LN_EPS 1e-5f

__device__ float g_dmT[DN * BN];    // [d][i]

typedef unsigned long long ull;
typedef unsigned int uint;

// ===========================================================================
// order-preserving float <-> uint encode
// ===========================================================================
__device__ __forceinline__ uint encf(float f) {
    uint u = __float_as_uint(f);
    return u ^ ((u & 0x80000000u) ? 0xFFFFFFFFu : 0x80000000u);
}
__device__ __forceinline__ float decf(uint u) {
    u ^= (u & 0x80000000u) ? 0x80000000u : 0xFFFFFFFFu;
    return __uint_as_float(u);
}

// ===========================================================================
// K1: per-column mean |x_i - x_j| via hybrid bitonic sort (R12-verbatim),
// plus griddepcontrol.launch_dependents after dmT writes (PDL producer).
// 128 blocks, 512 threads. __maxnreg__(48) to allow tail co-residency.
// ===========================================================================
__device__ __forceinline__ void g64(int t) {
    asm volatile("bar.sync %0, 64;"  :: "r"(1 + (t >> 6)) : "memory");
}
__device__ __forceinline__ void g128(int t) {
    asm volatile("bar.sync %0, 128;" :: "r"(9 + (t >> 7)) : "memory");
}
__device__ __forceinline__ void g256(int t) {
    asm volatile("bar.sync %0, 256;" :: "r"(13 + (t >> 8)) : "memory");
}

template<int K, int J>
__device__ __forceinline__ void sstage(uint* __restrict__ sv, int t) {
    int i = ((t & ~(J - 1)) << 1) | (t & (J - 1));
    int ixj = i | J;
    uint a = sv[i];
    uint b = sv[ixj];
    if ((a > b) == ((i & K) == 0)) { sv[i] = b; sv[ixj] = a; }
}

__device__ __forceinline__ void rtail(uint& r0, uint& r1, int p0, bool up) {
    uint lo = min(r0, r1), hi = max(r0, r1);
    r0 = up ? lo : hi;
    r1 = up ? hi : lo;
    #pragma unroll
    for (int j = 16; j > 0; j >>= 1) {
        bool km = (((p0 & j) == 0) == up);
        uint o0 = __shfl_xor_sync(0xffffffffu, r0, j);
        r0 = km ? min(r0, o0) : max(r0, o0);
        uint o1 = __shfl_xor_sync(0xffffffffu, r1, j);
        r1 = km ? min(r1, o1) : max(r1, o1);
    }
}

__global__ void __maxnreg__(48)
col_absdiff_mean_kernel(const float* __restrict__ x, float* __restrict__ dmT)
{
    __shared__ uint  sv[BN];
    __shared__ float ps[BN];
    __shared__ float wsum[16];

    const int d = blockIdx.x;
    const int t = threadIdx.x;
    const int lane = t & 31;
    const int w = t >> 5;
    const int p0 = (w << 6) + lane;
    const int p1 = p0 + 32;

    const float f0 = x[p0 * DN + d];
    const float f1 = x[p1 * DN + d];
    const uint e0 = encf(f0);
    const uint e1 = encf(f1);
    uint r0 = e0, r1 = e1;

    // phase A: k = 2..64, registers/shfl only
    #pragma unroll
    for (int k = 2; k <= 64; k <<= 1) {
        #pragma unroll
        for (int j = k >> 1; j > 0; j >>= 1) {
            if (j == 32) {
                bool up = ((p0 & k) == 0);
                uint lo = min(r0, r1), hi = max(r0, r1);
                r0 = up ? lo : hi;
                r1 = up ? hi : lo;
            } else {
                bool up0 = ((p0 & k) == 0);
                bool km0 = (((p0 & j) == 0) == up0);
                uint o0 = __shfl_xor_sync(0xffffffffu, r0, j);
                r0 = km0 ? min(r0, o0) : max(r0, o0);
                bool up1 = ((p1 & k) == 0);
                bool km1 = (((p1 & j) == 0) == up1);
                uint o1 = __shfl_xor_sync(0xffffffffu, r1, j);
                r1 = km1 ? min(r1, o1) : max(r1, o1);
            }
        }
    }

    // phase B
    sv[p0] = r0; sv[p1] = r1;
    g64(t);
    sstage<128, 64>(sv, t);
    g64(t);
    r0 = sv[p0]; r1 = sv[p1];
    rtail(r0, r1, p0, (p0 & 128) == 0);

    sv[p0] = r0; sv[p1] = r1;
    g128(t);
    sstage<256, 128>(sv, t);
    g128(t);
    sstage<256, 64>(sv, t);
    g64(t);
    r0 = sv[p0]; r1 = sv[p1];
    rtail(r0, r1, p0, (p0 & 256) == 0);

    sv[p0] = r0; sv[p1] = r1;
    g256(t);
    sstage<512, 256>(sv, t);
    g256(t);
    sstage<512, 128>(sv, t);
    g128(t);
    sstage<512, 64>(sv, t);
    g64(t);
    r0 = sv[p0]; r1 = sv[p1];
    rtail(r0, r1, p0, (p0 & 512) == 0);

    sv[p0] = r0; sv[p1] = r1;
    __syncthreads();
    sstage<1024, 512>(sv, t);
    __syncthreads();
    sstage<1024, 256>(sv, t);
    g256(t);
    sstage<1024, 128>(sv, t);
    g128(t);
    sstage<1024, 64>(sv, t);
    g64(t);
    r0 = sv[p0]; r1 = sv[p1];
    rtail(r0, r1, p0, true);

    // sorted keys + prefix sums
    sv[p0] = r0;
    sv[p1] = r1;
    float v0 = decf(r0);
    float v1 = decf(r1);

    float s0 = v0;
    #pragma unroll
    for (int o = 1; o < 32; o <<= 1) {
        float n = __shfl_up_sync(0xffffffffu, s0, o);
        if (lane >= o) s0 += n;
    }
    float T0 = __shfl_sync(0xffffffffu, s0, 31);
    float s1 = v1;
    #pragma unroll
    for (int o = 1; o < 32; o <<= 1) {
        float n = __shfl_up_sync(0xffffffffu, s1, o);
        if (lane >= o) s1 += n;
    }
    float T1 = __shfl_sync(0xffffffffu, s1, 31);
    if (lane == 0) wsum[w] = T0 + T1;
    __syncthreads();
    if (t < 16) {
        float v = wsum[t];
        #pragma unroll
        for (int o = 1; o < 16; o <<= 1) {
            float n = __shfl_up_sync(0x0000ffffu, v, o);
            if (t >= o) v += n;
        }
        wsum[t] = v;
    }
    __syncthreads();
    const float S = wsum[15];
    const float wexcl = (w == 0) ? 0.0f : wsum[w - 1];
    ps[p0] = wexcl + s0;
    ps[p1] = wexcl + T0 + s1;
    __syncthreads();

    // binary-search ranks; closed-form coalesced writes
    {
        int q = 0;
        #pragma unroll
        for (int st = 512; st > 0; st >>= 1) {
            int nq = q + st;
            if (sv[nq - 1] < e0) q = nq;
        }
        float o = f0 * (float)(2 * (q + 1) - BN) + S - 2.0f * ps[q];
        dmT[d * BN + p0] = o * (1.0f / (float)BN);
    }
    {
        int q = 0;
        #pragma unroll
        for (int st = 512; st > 0; st >>= 1) {
            int nq = q + st;
            if (sv[nq - 1] < e1) q = nq;
        }
        float o = f1 * (float)(2 * (q + 1) - BN) + S - 2.0f * ps[q];
        dmT[d * BN + p1] = o * (1.0f / (float)BN);
    }

    // PDL: signal dependents (dmT for this CTA is written)
    __threadfence();
    asm volatile("griddepcontrol.launch_dependents;" ::: "memory");
}

// ===========================================================================
// tail (PDL consumer): 128 blocks x 8 rows, 512 threads, __maxnreg__(72).
// PRE-SYNC (independent of dmT): stage xs/cb, tau, mv3 (x@Wr).
// griddepcontrol.wait, then: stage ds, mv1 (dm@Wd)/tau, mv2, LN, out.
// ===========================================================================
__device__ __forceinline__ ull fma2(ull a, ull b, ull c) {
    ull d;
    asm("fma.rn.f32x2 %0, %1, %2, %3;" : "=l"(d) : "l"(a), "l"(b), "l"(c));
    return d;
}
__device__ __forceinline__ ull add2(ull a, ull b) {
    ull d;
    asm("add.rn.f32x2 %0, %1, %2;" : "=l"(d) : "l"(a), "l"(b));
    return d;
}
__device__ __forceinline__ ull dup2(float w) {
    ull d;
    asm("mov.b64 %0, {%1, %1};" : "=l"(d) : "r"(__float_as_uint(w)));
    return d;
}

#define CHW 68
#define IDX(k, r) ((((k) >> 3) * CHW) + (((k) & 7) << 3) + (r))

__device__ __forceinline__ void load_w4(const float* __restrict__ W,
                                        int colbase, int k0, float4 wv[4])
{
    #pragma unroll
    for (int c = 0; c < 4; c++)
        wv[c] = *(const float4*)(W + (colbase + c) * DN + k0);
}

__device__ __forceinline__ void mv_acc4(const float* __restrict__ ip, int kb,
                                        const float4 wv[4], ull A[16])
{
    #pragma unroll
    for (int kl = 0; kl < 4; kl++) {
        ulonglong2 q0 = *(const ulonglong2*)(ip + (kb + kl) * 8);
        ulonglong2 q1 = *(const ulonglong2*)(ip + (kb + kl) * 8 + 4);
        #pragma unroll
        for (int c = 0; c < 4; c++) {
            ull w2 = dup2(((const float*)&wv[c])[kl]);
            A[c * 4 + 0] = fma2(q0.x, w2, A[c * 4 + 0]);
            A[c * 4 + 1] = fma2(q0.y, w2, A[c * 4 + 1]);
            A[c * 4 + 2] = fma2(q1.x, w2, A[c * 4 + 2]);
            A[c * 4 + 3] = fma2(q1.y, w2, A[c * 4 + 3]);
        }
    }
}

__device__ __forceinline__ void butterfly16(ull A[16], int m)
{
    #pragma unroll
    for (int j = 0; j < 8; j++) {
        ull s = (m & 8) ? A[j] : A[j + 8];
        ull c = __shfl_xor_sync(0xffffffffu, s, 8);
        A[j] = add2((m & 8) ? A[j + 8] : A[j], c);
    }
    #pragma unroll
    for (int j = 0; j < 4; j++) {
        ull s = (m & 4) ? A[j] : A[j + 4];
        ull c = __shfl_xor_sync(0xffffffffu, s, 4);
        A[j] = add2((m & 4) ? A[j + 4] : A[j], c);
    }
    #pragma unroll
    for (int j = 0; j < 2; j++) {
        ull s = (m & 2) ? A[j] : A[j + 2];
        ull c = __shfl_xor_sync(0xffffffffu, s, 2);
        A[j] = add2((m & 2) ? A[j + 2] : A[j], c);
    }
    {
        ull s = (m & 1) ? A[0] : A[1];
        ull c = __shfl_xor_sync(0xffffffffu, s, 1);
        A[0] = add2((m & 1) ? A[1] : A[0], c);
    }
}

__global__ void __maxnreg__(72)
tail_kernel(
    const float* __restrict__ x,
    const float* __restrict__ Wd, const float* __restrict__ bd,
    const float* __restrict__ Wt, const float* __restrict__ bt,
    const float* __restrict__ Wa, const float* __restrict__ ba,
    const float* __restrict__ Wr, const float* __restrict__ br,
    const float* __restrict__ gamma, const float* __restrict__ beta,
    const float* __restrict__ dmT, float* __restrict__ out)
{
    __shared__ __align__(16) float xs[16 * CHW];
    __shared__ __align__(16) float ds[16 * CHW];
    __shared__ __align__(16) float hs[16 * CHW];
    __shared__ float Wt_s[128], bd_s[128], ba_s[128], br_s[128], g_s[128], be_s[128];
    __shared__ float redS[128], redQ[128];
    __shared__ float rtau_s[8];
    __shared__ float musig[16];

    const int t = threadIdx.x;
    const int lane = t & 31;
    const int m = lane & 15;
    const int colbase = (t >> 4) * 4;
    const int k0 = m * 8;
    const int i0 = blockIdx.x * 8;
    const int col = colbase + (m >> 2);
    const int r0 = 2 * (m & 3);

    // ---------------- PRE-SYNC: independent of dmT ----------------
    float4 wv[4];
    load_w4(Wr, colbase, k0, wv);

    #pragma unroll
    for (int it = 0; it < 2; it++) {
        int e = t + it * 512;
        int r = e >> 7, k = e & 127;
        xs[IDX(k, r)] = x[(i0 + r) * DN + k];
    }
    if (t < 128)       { Wt_s[t] = Wt[t];             g_s[t] = gamma[t]; }
    else if (t < 256)  { bd_s[t - 128] = bd[t - 128]; be_s[t - 128] = beta[t - 128]; }
    else if (t < 384)  { ba_s[t - 256] = ba[t - 256]; }
    else               { br_s[t - 384] = br[t - 384]; }
    __syncthreads();

    // tau partials
    if (t < 128) {
        int o = IDX(t, 0);
        float4 xa = *(const float4*)(xs + o);
        float4 xb = *(const float4*)(xs + o + 4);
        float wt = Wt_s[t];
        float pr[8] = { xa.x * wt, xa.y * wt, xa.z * wt, xa.w * wt,
                        xb.x * wt, xb.y * wt, xb.z * wt, xb.w * wt };
        #pragma unroll
        for (int r = 0; r < 8; r++) {
            float v = pr[r];
            #pragma unroll
            for (int o2 = 16; o2; o2 >>= 1) v += __shfl_xor_sync(0xffffffffu, v, o2);
            if (lane == 0) redS[(t >> 5) * 8 + r] = v;
        }
    }
    __syncthreads();
    if (t < 8) {
        float z = redS[t] + redS[8 + t] + redS[16 + t] + redS[24 + t] + bt[0];
        float sp = fmaxf(z, 0.0f) + log1pf(expf(-fabsf(z)));
        rtau_s[t] = 1.0f / (fmaxf(sp, 0.01f) + 1.0f);
    }

    ull A[16];
    const float* xsp = xs + m * CHW;
    const float* dsp = ds + m * CHW;
    const float* hsp = hs + m * CHW;

    // mv3: x @ Wr^T (fully independent of dmT)
    #pragma unroll
    for (int i = 0; i < 16; i++) A[i] = 0ull;
    mv_acc4(xsp, 0, wv, A);
    load_w4(Wr, colbase, k0 + 4, wv);
    mv_acc4(xsp, 4, wv, A);
    butterfly16(A, m);
    float s3a = __uint_as_float((uint)A[0]);
    float s3b = __uint_as_float((uint)(A[0] >> 32));

    // prefetch Wd lo
    load_w4(Wd, colbase, k0, wv);

    // ---------------- PDL sync: dmT now valid ----------------
    asm volatile("griddepcontrol.wait;" ::: "memory");

    // stage ds from dmT
    #pragma unroll
    for (int it = 0; it < 2; it++) {
        int e = t + it * 512;
        int k = e >> 3, r = e & 7;
        ds[IDX(k, r)] = dmT[k * BN + i0 + r];
    }
    __syncthreads();                        // ds ready (rtau also covered)

    // mv1: dm @ Wd^T
    #pragma unroll
    for (int i = 0; i < 16; i++) A[i] = 0ull;
    mv_acc4(dsp, 0, wv, A);
    load_w4(Wd, colbase, k0 + 4, wv);
    mv_acc4(dsp, 4, wv, A);
    butterfly16(A, m);
    float s1a = __uint_as_float((uint)A[0]);
    float s1b = __uint_as_float((uint)(A[0] >> 32));

    {
        float bdv = bd_s[col];
        float hm0 = (s1a + bdv) * rtau_s[r0];
        float hm1 = (s1b + bdv) * rtau_s[r0 + 1];
        *(float2*)(hs + IDX(col, r0)) = make_float2(hm0, hm1);
    }
    load_w4(Wa, colbase, k0, wv);
    __syncthreads();                        // hs ready

    // mv2: hm @ Wa^T
    #pragma unroll
    for (int i = 0; i < 16; i++) A[i] = 0ull;
    mv_acc4(hsp, 0, wv, A);
    load_w4(Wa, colbase, k0 + 4, wv);
    mv_acc4(hsp, 4, wv, A);
    butterfly16(A, m);
    float s2a = __uint_as_float((uint)A[0]);
    float s2b = __uint_as_float((uint)(A[0] >> 32));

    float bav = ba_s[col], brv = br_s[col];
    float y0 = fmaxf(s2a + bav, 0.0f) + s3a + brv;
    float y1 = fmaxf(s2b + bav, 0.0f) + s3b + brv;

    // LayerNorm
    float sa = y0, qa = y0 * y0, sb2 = y1, qb2 = y1 * y1;
    #pragma unroll
    for (int mk = 4; mk <= 16; mk <<= 1) {
        sa  += __shfl_xor_sync(0xffffffffu, sa, mk);
        qa  += __shfl_xor_sync(0xffffffffu, qa, mk);
        sb2 += __shfl_xor_sync(0xffffffffu, sb2, mk);
        qb2 += __shfl_xor_sync(0xffffffffu, qb2, mk);
    }
    if (lane < 4) {
        int wp = t >> 5;
        redS[wp * 8 + r0] = sa;      redQ[wp * 8 + r0] = qa;
        redS[wp * 8 + r0 + 1] = sb2; redQ[wp * 8 + r0 + 1] = qb2;
    }
    __syncthreads();
    if (t < 8) {
        float ss = 0.0f, qs = 0.0f;
        #pragma unroll
        for (int wp = 0; wp < 16; wp++) { ss += redS[wp * 8 + t]; qs += redQ[wp * 8 + t]; }
        float mu = ss * (1.0f / 128.0f);
        float var = qs * (1.0f / 128.0f) - mu * mu;
        musig[2 * t] = mu;
        musig[2 * t + 1] = rsqrtf(var + LN_EPS);
    }
    __syncthreads();
    float gv = g_s[col], bv = be_s[col];
    out[(i0 + r0) * HN + col]     = (y0 - musig[2 * r0]) * musig[2 * r0 + 1] * gv + bv;
    out[(i0 + r0 + 1) * HN + col] = (y1 - musig[2 * r0 + 2]) * musig[2 * r0 + 3] * gv + bv;
}

// ===========================================================================
extern "C" void kernel_launch(void* const* d_in, const int* in_sizes, int n_in,
                              void* d_out, int out_size)
{
    const float* x     = (const float*)d_in[0];
    const float* Wd    = (const float*)d_in[1];
    const float* bd    = (const float*)d_in[2];
    const float* Wt    = (const float*)d_in[3];
    const float* bt    = (const float*)d_in[4];
    const float* Wa    = (const float*)d_in[5];
    const float* ba    = (const float*)d_in[6];
    const float* Wr    = (const float*)d_in[7];
    const float* br    = (const float*)d_in[8];
    const float* gamma = (const float*)d_in[9];
    const float* beta  = (const float*)d_in[10];
    float* out = (float*)d_out;

    float* dmT = nullptr;
    cudaGetSymbolAddress((void**)&dmT, g_dmT);

    col_absdiff_mean_kernel<<<DN, 512>>>(x, dmT);

    // tail with programmatic dependent launch (overlaps K1's execution)
    cudaLaunchConfig_t cfg = {};
    cfg.gridDim = dim3(BN / 8);
    cfg.blockDim = dim3(512);
    cfg.dynamicSmemBytes = 0;
    cfg.stream = 0;
    cudaLaunchAttribute attrs[1];
    attrs[0].id = cudaLaunchAttributeProgrammaticStreamSerialization;
    attrs[0].val.programmaticStreamSerializationAllowed = 1;
    cfg.attrs = attrs;
    cfg.numAttrs = 1;
    cudaLaunchKernelEx(&cfg, tail_kernel,
                       x, Wd, bd, Wt, bt, Wa, ba, Wr, br, gamma, beta,
                       (const float*)dmT, out);
}

// round 17
// speedup vs baseline: 1.1404x; 1.0152x over previous
#include <cuda_runtime.h>
#include <math.h>

#define BN 1024
#define DN 128
#define HN 128
#define LN_EPS 1e-5f

__device__ float g_dmT[DN * BN];    // [d][i]

typedef unsigned long long ull;
typedef unsigned int uint;

// ===========================================================================
// order-preserving float <-> uint encode
// ===========================================================================
__device__ __forceinline__ uint encf(float f) {
    uint u = __float_as_uint(f);
    return u ^ ((u & 0x80000000u) ? 0xFFFFFFFFu : 0x80000000u);
}
__device__ __forceinline__ float decf(uint u) {
    u ^= (u & 0x80000000u) ? 0x80000000u : 0xFFFFFFFFu;
    return __uint_as_float(u);
}

// ===========================================================================
// K1: per-column mean |x_i - x_j| via hybrid bitonic sort (R12-verbatim).
// 128 blocks, 512 threads, 2 keys/thread; named barriers per dependent group.
// ===========================================================================
__device__ __forceinline__ void g64(int t) {
    asm volatile("bar.sync %0, 64;"  :: "r"(1 + (t >> 6)) : "memory");
}
__device__ __forceinline__ void g128(int t) {
    asm volatile("bar.sync %0, 128;" :: "r"(9 + (t >> 7)) : "memory");
}
__device__ __forceinline__ void g256(int t) {
    asm volatile("bar.sync %0, 256;" :: "r"(13 + (t >> 8)) : "memory");
}

template<int K, int J>
__device__ __forceinline__ void sstage(uint* __restrict__ sv, int t) {
    int i = ((t & ~(J - 1)) << 1) | (t & (J - 1));
    int ixj = i | J;
    uint a = sv[i];
    uint b = sv[ixj];
    if ((a > b) == ((i & K) == 0)) { sv[i] = b; sv[ixj] = a; }
}

__device__ __forceinline__ void rtail(uint& r0, uint& r1, int p0, bool up) {
    uint lo = min(r0, r1), hi = max(r0, r1);
    r0 = up ? lo : hi;
    r1 = up ? hi : lo;
    #pragma unroll
    for (int j = 16; j > 0; j >>= 1) {
        bool km = (((p0 & j) == 0) == up);
        uint o0 = __shfl_xor_sync(0xffffffffu, r0, j);
        r0 = km ? min(r0, o0) : max(r0, o0);
        uint o1 = __shfl_xor_sync(0xffffffffu, r1, j);
        r1 = km ? min(r1, o1) : max(r1, o1);
    }
}

__global__ __launch_bounds__(512) void col_absdiff_mean_kernel(
    const float* __restrict__ x, float* __restrict__ dmT)
{
    __shared__ uint  sv[BN];
    __shared__ float ps[BN];
    __shared__ float wsum[16];

    const int d = blockIdx.x;
    const int t = threadIdx.x;
    const int lane = t & 31;
    const int w = t >> 5;
    const int p0 = (w << 6) + lane;
    const int p1 = p0 + 32;

    const float f0 = x[p0 * DN + d];
    const float f1 = x[p1 * DN + d];
    const uint e0 = encf(f0);
    const uint e1 = encf(f1);
    uint r0 = e0, r1 = e1;

    #pragma unroll
    for (int k = 2; k <= 64; k <<= 1) {
        #pragma unroll
        for (int j = k >> 1; j > 0; j >>= 1) {
            if (j == 32) {
                bool up = ((p0 & k) == 0);
                uint lo = min(r0, r1), hi = max(r0, r1);
                r0 = up ? lo : hi;
                r1 = up ? hi : lo;
            } else {
                bool up0 = ((p0 & k) == 0);
                bool km0 = (((p0 & j) == 0) == up0);
                uint o0 = __shfl_xor_sync(0xffffffffu, r0, j);
                r0 = km0 ? min(r0, o0) : max(r0, o0);
                bool up1 = ((p1 & k) == 0);
                bool km1 = (((p1 & j) == 0) == up1);
                uint o1 = __shfl_xor_sync(0xffffffffu, r1, j);
                r1 = km1 ? min(r1, o1) : max(r1, o1);
            }
        }
    }

    sv[p0] = r0; sv[p1] = r1;
    g64(t);
    sstage<128, 64>(sv, t);
    g64(t);
    r0 = sv[p0]; r1 = sv[p1];
    rtail(r0, r1, p0, (p0 & 128) == 0);

    sv[p0] = r0; sv[p1] = r1;
    g128(t);
    sstage<256, 128>(sv, t);
    g128(t);
    sstage<256, 64>(sv, t);
    g64(t);
    r0 = sv[p0]; r1 = sv[p1];
    rtail(r0, r1, p0, (p0 & 256) == 0);

    sv[p0] = r0; sv[p1] = r1;
    g256(t);
    sstage<512, 256>(sv, t);
    g256(t);
    sstage<512, 128>(sv, t);
    g128(t);
    sstage<512, 64>(sv, t);
    g64(t);
    r0 = sv[p0]; r1 = sv[p1];
    rtail(r0, r1, p0, (p0 & 512) == 0);

    sv[p0] = r0; sv[p1] = r1;
    __syncthreads();
    sstage<1024, 512>(sv, t);
    __syncthreads();
    sstage<1024, 256>(sv, t);
    g256(t);
    sstage<1024, 128>(sv, t);
    g128(t);
    sstage<1024, 64>(sv, t);
    g64(t);
    r0 = sv[p0]; r1 = sv[p1];
    rtail(r0, r1, p0, true);

    sv[p0] = r0;
    sv[p1] = r1;
    float v0 = decf(r0);
    float v1 = decf(r1);

    float s0 = v0;
    #pragma unroll
    for (int o = 1; o < 32; o <<= 1) {
        float n = __shfl_up_sync(0xffffffffu, s0, o);
        if (lane >= o) s0 += n;
    }
    float T0 = __shfl_sync(0xffffffffu, s0, 31);
    float s1 = v1;
    #pragma unroll
    for (int o = 1; o < 32; o <<= 1) {
        float n = __shfl_up_sync(0xffffffffu, s1, o);
        if (lane >= o) s1 += n;
    }
    float T1 = __shfl_sync(0xffffffffu, s1, 31);
    if (lane == 0) wsum[w] = T0 + T1;
    __syncthreads();
    if (t < 16) {
        float v = wsum[t];
        #pragma unroll
        for (int o = 1; o < 16; o <<= 1) {
            float n = __shfl_up_sync(0x0000ffffu, v, o);
            if (t >= o) v += n;
        }
        wsum[t] = v;
    }
    __syncthreads();
    const float S = wsum[15];
    const float wexcl = (w == 0) ? 0.0f : wsum[w - 1];
    ps[p0] = wexcl + s0;
    ps[p1] = wexcl + T0 + s1;
    __syncthreads();

    {
        int q = 0;
        #pragma unroll
        for (int st = 512; st > 0; st >>= 1) {
            int nq = q + st;
            if (sv[nq - 1] < e0) q = nq;
        }
        float o = f0 * (float)(2 * (q + 1) - BN) + S - 2.0f * ps[q];
        dmT[d * BN + p0] = o * (1.0f / (float)BN);
    }
    {
        int q = 0;
        #pragma unroll
        for (int st = 512; st > 0; st >>= 1) {
            int nq = q + st;
            if (sv[nq - 1] < e1) q = nq;
        }
        float o = f1 * (float)(2 * (q + 1) - BN) + S - 2.0f * ps[q];
        dmT[d * BN + p1] = o * (1.0f / (float)BN);
    }
}

// ===========================================================================
// tail: warp-specialized, 128 blocks x 8 rows, 1024 threads.
// Group A (t<512): stage ds -> mv1 -> hs -> mv2 -> +y3s -> LayerNorm -> out.
// Group B (t>=512): stage xs/cb -> tau -> mv3 (x@Wr + br) -> y3s.
// Cross-group hand-offs via 3 block-wide __syncthreads (both groups call 3).
// ===========================================================================
__device__ __forceinline__ ull fma2(ull a, ull b, ull c) {
    ull d;
    asm("fma.rn.f32x2 %0, %1, %2, %3;" : "=l"(d) : "l"(a), "l"(b), "l"(c));
    return d;
}
__device__ __forceinline__ ull add2(ull a, ull b) {
    ull d;
    asm("add.rn.f32x2 %0, %1, %2;" : "=l"(d) : "l"(a), "l"(b));
    return d;
}
__device__ __forceinline__ ull dup2(float w) {
    ull d;
    asm("mov.b64 %0, {%1, %1};" : "=l"(d) : "r"(__float_as_uint(w)));
    return d;
}

#define CHW 68
#define IDX(k, r) ((((k) >> 3) * CHW) + (((k) & 7) << 3) + (r))

__device__ __forceinline__ void load_w4(const float* __restrict__ W,
                                        int colbase, int k0, float4 wv[4])
{
    #pragma unroll
    for (int c = 0; c < 4; c++)
        wv[c] = *(const float4*)(W + (colbase + c) * DN + k0);
}

__device__ __forceinline__ void mv_acc4(const float* __restrict__ ip, int kb,
                                        const float4 wv[4], ull A[16])
{
    #pragma unroll
    for (int kl = 0; kl < 4; kl++) {
        ulonglong2 q0 = *(const ulonglong2*)(ip + (kb + kl) * 8);
        ulonglong2 q1 = *(const ulonglong2*)(ip + (kb + kl) * 8 + 4);
        #pragma unroll
        for (int c = 0; c < 4; c++) {
            ull w2 = dup2(((const float*)&wv[c])[kl]);
            A[c * 4 + 0] = fma2(q0.x, w2, A[c * 4 + 0]);
            A[c * 4 + 1] = fma2(q0.y, w2, A[c * 4 + 1]);
            A[c * 4 + 2] = fma2(q1.x, w2, A[c * 4 + 2]);
            A[c * 4 + 3] = fma2(q1.y, w2, A[c * 4 + 3]);
        }
    }
}

__device__ __forceinline__ void butterfly16(ull A[16], int m)
{
    #pragma unroll
    for (int j = 0; j < 8; j++) {
        ull s = (m & 8) ? A[j] : A[j + 8];
        ull c = __shfl_xor_sync(0xffffffffu, s, 8);
        A[j] = add2((m & 8) ? A[j + 8] : A[j], c);
    }
    #pragma unroll
    for (int j = 0; j < 4; j++) {
        ull s = (m & 4) ? A[j] : A[j + 4];
        ull c = __shfl_xor_sync(0xffffffffu, s, 4);
        A[j] = add2((m & 4) ? A[j + 4] : A[j], c);
    }
    #pragma unroll
    for (int j = 0; j < 2; j++) {
        ull s = (m & 2) ? A[j] : A[j + 2];
        ull c = __shfl_xor_sync(0xffffffffu, s, 2);
        A[j] = add2((m & 2) ? A[j + 2] : A[j], c);
    }
    {
        ull s = (m & 1) ? A[0] : A[1];
        ull c = __shfl_xor_sync(0xffffffffu, s, 1);
        A[0] = add2((m & 1) ? A[1] : A[0], c);
    }
}

__global__ __launch_bounds__(1024, 1) void tail_kernel(
    const float* __restrict__ x,
    const float* __restrict__ Wd, const float* __restrict__ bd,
    const float* __restrict__ Wt, const float* __restrict__ bt,
    const float* __restrict__ Wa, const float* __restrict__ ba,
    const float* __restrict__ Wr, const float* __restrict__ br,
    const float* __restrict__ gamma, const float* __restrict__ beta,
    const float* __restrict__ dmT, float* __restrict__ out)
{
    __shared__ __align__(16) float xs[16 * CHW];
    __shared__ __align__(16) float ds[16 * CHW];
    __shared__ __align__(16) float hs[16 * CHW];
    __shared__ float y3s[HN * 8];           // [col*8 + r]
    __shared__ float Wt_s[128], bd_s[128], ba_s[128], br_s[128], g_s[128], be_s[128];
    __shared__ float redS[128], redQ[128];
    __shared__ float rtau_s[8];
    __shared__ float musig[16];

    const int t = threadIdx.x;
    const int i0 = blockIdx.x * 8;
    const bool isA = (t < 512);
    const int tg = isA ? t : (t - 512);
    const int lane = tg & 31;
    const int m = lane & 15;
    const int colbase = (tg >> 4) * 4;
    const int k0 = m * 8;
    const int col = colbase + (m >> 2);
    const int r0 = 2 * (m & 3);

    float4 wv[4];
    ull A[16];

    if (isA) {
        // --- A: prefetch Wd, stage ds from dmT ---
        load_w4(Wd, colbase, k0, wv);
        #pragma unroll
        for (int it = 0; it < 2; it++) {
            int e = tg + it * 512;
            int k = e >> 3, r = e & 7;
            ds[IDX(k, r)] = dmT[k * BN + i0 + r];
        }
    } else {
        // --- B: prefetch Wr, stage xs + cb ---
        load_w4(Wr, colbase, k0, wv);
        #pragma unroll
        for (int it = 0; it < 2; it++) {
            int e = tg + it * 512;
            int r = e >> 7, k = e & 127;
            xs[IDX(k, r)] = x[(i0 + r) * DN + k];
        }
        if (tg < 128)       { Wt_s[tg] = Wt[tg];              g_s[tg] = gamma[tg]; }
        else if (tg < 256)  { bd_s[tg - 128] = bd[tg - 128];  be_s[tg - 128] = beta[tg - 128]; }
        else if (tg < 384)  { ba_s[tg - 256] = ba[tg - 256]; }
        else                { br_s[tg - 384] = br[tg - 384]; }
    }
    __syncthreads();                        // #1: ds, xs, cb visible

    if (isA) {
        // --- A: mv1 (ds @ Wd^T) ---
        #pragma unroll
        for (int i = 0; i < 16; i++) A[i] = 0ull;
        const float* dsp = ds + m * CHW;
        mv_acc4(dsp, 0, wv, A);
        load_w4(Wd, colbase, k0 + 4, wv);
        mv_acc4(dsp, 4, wv, A);
        butterfly16(A, m);
        load_w4(Wa, colbase, k0, wv);       // prefetch Wa lo
    } else {
        // --- B: tau (warps 16-19: tg<128 = k index) ---
        if (tg < 128) {
            int o = IDX(tg, 0);
            float4 xa = *(const float4*)(xs + o);
            float4 xb = *(const float4*)(xs + o + 4);
            float wt = Wt_s[tg];
            float pr[8] = { xa.x * wt, xa.y * wt, xa.z * wt, xa.w * wt,
                            xb.x * wt, xb.y * wt, xb.z * wt, xb.w * wt };
            #pragma unroll
            for (int r = 0; r < 8; r++) {
                float v = pr[r];
                #pragma unroll
                for (int o2 = 16; o2; o2 >>= 1) v += __shfl_xor_sync(0xffffffffu, v, o2);
                if (lane == 0) redS[(tg >> 5) * 8 + r] = v;
            }
        }
        asm volatile("bar.sync 2, 512;" ::: "memory");   // B-scope
        if (tg < 8) {
            float z = redS[tg] + redS[8 + tg] + redS[16 + tg] + redS[24 + tg] + bt[0];
            float sp = fmaxf(z, 0.0f) + log1pf(expf(-fabsf(z)));
            rtau_s[tg] = 1.0f / (fmaxf(sp, 0.01f) + 1.0f);
        }
    }
    __syncthreads();                        // #2: rtau visible; A mv1 done

    if (isA) {
        // --- A: write hs = (s1 + bd) * rtau ---
        float s1a = __uint_as_float((uint)A[0]);
        float s1b = __uint_as_float((uint)(A[0] >> 32));
        float bdv = bd_s[col];
        float hm0 = (s1a + bdv) * rtau_s[r0];
        float hm1 = (s1b + bdv) * rtau_s[r0 + 1];
        *(float2*)(hs + IDX(col, r0)) = make_float2(hm0, hm1);
        asm volatile("bar.sync 1, 512;" ::: "memory");   // A-scope: hs ready

        // --- A: mv2 (hs @ Wa^T) ---
        #pragma unroll
        for (int i = 0; i < 16; i++) A[i] = 0ull;
        const float* hsp = hs + m * CHW;
        mv_acc4(hsp, 0, wv, A);
        load_w4(Wa, colbase, k0 + 4, wv);
        mv_acc4(hsp, 4, wv, A);
        butterfly16(A, m);
    } else {
        // --- B: mv3 (xs @ Wr^T), write y3s = s3 + br ---
        #pragma unroll
        for (int i = 0; i < 16; i++) A[i] = 0ull;
        const float* xsp = xs + m * CHW;
        mv_acc4(xsp, 0, wv, A);
        load_w4(Wr, colbase, k0 + 4, wv);
        mv_acc4(xsp, 4, wv, A);
        butterfly16(A, m);
        float brv = br_s[col];
        float s3a = __uint_as_float((uint)A[0]) + brv;
        float s3b = __uint_as_float((uint)(A[0] >> 32)) + brv;
        *(float2*)(y3s + col * 8 + r0) = make_float2(s3a, s3b);
    }
    __syncthreads();                        // #3: y3s visible; A mv2 done

    if (isA) {
        float s2a = __uint_as_float((uint)A[0]);
        float s2b = __uint_as_float((uint)(A[0] >> 32));
        float bav = ba_s[col];
        float2 y3 = *(const float2*)(y3s + col * 8 + r0);
        float y0 = fmaxf(s2a + bav, 0.0f) + y3.x;
        float y1 = fmaxf(s2b + bav, 0.0f) + y3.y;

        // LayerNorm (A-internal)
        float sa = y0, qa = y0 * y0, sb2 = y1, qb2 = y1 * y1;
        #pragma unroll
        for (int mk = 4; mk <= 16; mk <<= 1) {
            sa  += __shfl_xor_sync(0xffffffffu, sa, mk);
            qa  += __shfl_xor_sync(0xffffffffu, qa, mk);
            sb2 += __shfl_xor_sync(0xffffffffu, sb2, mk);
            qb2 += __shfl_xor_sync(0xffffffffu, qb2, mk);
        }
        if (lane < 4) {
            int wp = tg >> 5;
            redS[wp * 8 + r0] = sa;      redQ[wp * 8 + r0] = qa;
            redS[wp * 8 + r0 + 1] = sb2; redQ[wp * 8 + r0 + 1] = qb2;
        }
        asm volatile("bar.sync 1, 512;" ::: "memory");
        if (tg < 8) {
            float ss = 0.0f, qs = 0.0f;
            #pragma unroll
            for (int wp = 0; wp < 16; wp++) { ss += redS[wp * 8 + tg]; qs += redQ[wp * 8 + tg]; }
            float mu = ss * (1.0f / 128.0f);
            float var = qs * (1.0f / 128.0f) - mu * mu;
            musig[2 * tg] = mu;
            musig[2 * tg + 1] = rsqrtf(var + LN_EPS);
        }
        asm volatile("bar.sync 1, 512;" ::: "memory");
        float gv = g_s[col], bv = be_s[col];
        out[(i0 + r0) * HN + col]     = (y0 - musig[2 * r0]) * musig[2 * r0 + 1] * gv + bv;
        out[(i0 + r0 + 1) * HN + col] = (y1 - musig[2 * r0 + 2]) * musig[2 * r0 + 3] * gv + bv;
    }
}

// ===========================================================================
extern "C" void kernel_launch(void* const* d_in, const int* in_sizes, int n_in,
                              void* d_out, int out_size)
{
    const float* x     = (const float*)d_in[0];
    const float* Wd    = (const float*)d_in[1];
    const float* bd    = (const float*)d_in[2];
    const float* Wt    = (const float*)d_in[3];
    const float* bt    = (const float*)d_in[4];
    const float* Wa    = (const float*)d_in[5];
    const float* ba    = (const float*)d_in[6];
    const float* Wr    = (const float*)d_in[7];
    const float* br    = (const float*)d_in[8];
    const float* gamma = (const float*)d_in[9];
    const float* beta  = (const float*)d_in[10];
    float* out = (float*)d_out;

    float* dmT = nullptr;
    cudaGetSymbolAddress((void**)&dmT, g_dmT);

    col_absdiff_mean_kernel<<<DN, 512>>>(x, dmT);
    tail_kernel<<<BN / 8, 1024>>>(
        x, Wd, bd, Wt, bt, Wa, ba, Wr, br, gamma, beta, dmT, out);
}